// round 1
// baseline (speedup 1.0000x reference)
#include <cuda_runtime.h>
#include <cstdint>

// Problem constants
#define T_LEN 1000
#define B_SZ  512
#define C_IN  22
#define H_SZ  64
#define G4    256            // 4*H gates
#define BC    (B_SZ * C_IN)  // 11264
#define TH    (T_LEN * H_SZ) // 64000

typedef unsigned long long ull;

// Scratch: x transposed to [t][b][c] (45 MB, static device array — no allocs)
__device__ float g_xT[T_LEN * BC];

// ---------------------------------------------------------------------------
// Kernel 1: transpose x [B*C, T] -> xT [T, B*C]
// ---------------------------------------------------------------------------
__global__ void transpose_kernel(const float* __restrict__ x) {
    __shared__ float tile[32][33];
    const int tx = threadIdx.x, ty = threadIdx.y;
    const int t0 = blockIdx.x * 32;   // time
    const int r0 = blockIdx.y * 32;   // bc row (always in range: 352*32 == 11264)
#pragma unroll
    for (int i = 0; i < 32; i += 8) {
        int t = t0 + tx;
        int r = r0 + ty + i;
        if (t < T_LEN) tile[ty + i][tx] = x[r * T_LEN + t];
    }
    __syncthreads();
#pragma unroll
    for (int i = 0; i < 32; i += 8) {
        int t = t0 + ty + i;
        int r = r0 + tx;
        if (t < T_LEN) g_xT[t * BC + r] = tile[tx][ty + i];
    }
}

// ---------------------------------------------------------------------------
// Packed fp32x2 helpers (Blackwell FFMA2: only reachable via PTX fma.rn.f32x2)
// ---------------------------------------------------------------------------
__device__ __forceinline__ ull splat2(float w) {
    ull r;
    uint32_t u = __float_as_uint(w);
    asm("mov.b64 %0, {%1, %1};" : "=l"(r) : "r"(u));
    return r;
}
__device__ __forceinline__ void ffma2(ull& d, ull a, ull b) {
    asm("fma.rn.f32x2 %0, %1, %2, %3;" : "=l"(d) : "l"(a), "l"(b), "l"(d));
}
__device__ __forceinline__ void unpack2(ull v, float& lo, float& hi) {
    uint32_t ulo, uhi;
    asm("mov.b64 {%0, %1}, %2;" : "=r"(ulo), "=r"(uhi) : "l"(v));
    lo = __uint_as_float(ulo);
    hi = __uint_as_float(uhi);
}

__device__ __forceinline__ float fast_sigmoid(float v) {
    return __fdividef(1.f, 1.f + __expf(-v));
}
__device__ __forceinline__ float fast_tanh(float v) {
    v = fminf(fmaxf(v, -15.f), 15.f);   // guard exp overflow; tanh saturated anyway
    float e = __expf(2.f * v);
    return __fdividef(e - 1.f, e + 1.f);
}

// ---------------------------------------------------------------------------
// Kernel 2: fused LSTM (1000 steps) + FC accumulation + softmax
// grid = 128 blocks (4 batch rows each), 256 threads (one per gate column)
// ---------------------------------------------------------------------------
__global__ void __launch_bounds__(256, 1) lstm_fused(
    const float* __restrict__ W_ih, const float* __restrict__ W_hh,
    const float* __restrict__ b_ih, const float* __restrict__ b_hh,
    const float* __restrict__ W_fc, const float* __restrict__ b_fc,
    float* __restrict__ out)
{
    // h packed as (row0,row1) and (row2,row3) fp32 pairs
    __shared__ __align__(16) ull h01[H_SZ];
    __shared__ __align__(16) ull h23[H_SZ];
    __shared__ __align__(16) ull x01[24];   // entries 22,23 = zero pad
    __shared__ __align__(16) ull x23[24];
    __shared__ float g_sh[4][G4];           // gate exchange / final scratch
    __shared__ float logits_sh[4][4];

    const int j  = threadIdx.x;             // gate column 0..255
    const int r0 = blockIdx.x * 4;          // first batch row of this CTA

    // --- weights for gate column j into registers ---
    float whh[H_SZ];
    const float4* wp = reinterpret_cast<const float4*>(W_hh + j * H_SZ);
#pragma unroll
    for (int k = 0; k < 16; k++) {
        float4 v = wp[k];
        whh[4*k+0] = v.x; whh[4*k+1] = v.y; whh[4*k+2] = v.z; whh[4*k+3] = v.w;
    }
    float wih[24];
#pragma unroll
    for (int c = 0; c < 22; c++) wih[c] = W_ih[j * 22 + c];
    wih[22] = 0.f; wih[23] = 0.f;

    const ull bias2 = splat2(b_ih[j] + b_hh[j]);

    // --- init shared state ---
    if (j < 64)          h01[j]      = 0ull;
    else if (j < 128)    h23[j - 64] = 0ull;
    else if (j == 128) { x01[22] = 0ull; x01[23] = 0ull; x23[22] = 0ull; x23[23] = 0ull; }

    // --- per-thread recurrent state: (batch row r_upd, hidden unit hidx) ---
    const int r_upd = j >> 6;
    const int hidx  = j & 63;
    float c_state = 0.f;
    float p0 = 0.f, p1 = 0.f, p2 = 0.f, p3 = 0.f;   // FC partials for 4 classes

    // prefetch W_fc for t=0
    const float* pf0 = W_fc + hidx;
    float wf0 = pf0[0], wf1 = pf0[TH], wf2 = pf0[2*TH], wf3 = pf0[3*TH];

    const float* xrow = g_xT + r0 * C_IN;

    for (int t = 0; t < T_LEN; t++) {
        // stage x_t for the 4 batch rows (88 floats, contiguous in gmem)
        if (j < 88) {
            float v = xrow[t * BC + j];
            int rr = j / 22, cc = j - rr * 22;
            float* dst = (rr < 2) ? (float*)&x01[cc] : (float*)&x23[cc];
            dst[rr & 1] = v;
        }
        __syncthreads();   // x + h (prev step) visible

        // gates for 4 rows, packed in fp32x2 pairs
        ull a01 = bias2, a23 = bias2;
        const ulonglong2* hp01 = reinterpret_cast<const ulonglong2*>(h01);
        const ulonglong2* hp23 = reinterpret_cast<const ulonglong2*>(h23);
#pragma unroll
        for (int kk = 0; kk < 32; kk++) {
            ulonglong2 hA = hp01[kk];
            ulonglong2 hB = hp23[kk];
            ull w0 = splat2(whh[2*kk]);
            ffma2(a01, w0, hA.x); ffma2(a23, w0, hB.x);
            ull w1 = splat2(whh[2*kk + 1]);
            ffma2(a01, w1, hA.y); ffma2(a23, w1, hB.y);
        }
        const ulonglong2* xp01 = reinterpret_cast<const ulonglong2*>(x01);
        const ulonglong2* xp23 = reinterpret_cast<const ulonglong2*>(x23);
#pragma unroll
        for (int cc = 0; cc < 12; cc++) {
            ulonglong2 xA = xp01[cc];
            ulonglong2 xB = xp23[cc];
            ull w0 = splat2(wih[2*cc]);
            ffma2(a01, w0, xA.x); ffma2(a23, w0, xB.x);
            ull w1 = splat2(wih[2*cc + 1]);
            ffma2(a01, w1, xA.y); ffma2(a23, w1, xB.y);
        }
        float v0, v1, v2, v3;
        unpack2(a01, v0, v1);
        unpack2(a23, v2, v3);
        g_sh[0][j] = v0; g_sh[1][j] = v1; g_sh[2][j] = v2; g_sh[3][j] = v3;
        __syncthreads();   // gates visible

        // state update for (r_upd, hidx)
        float gi = g_sh[r_upd][hidx];
        float gf = g_sh[r_upd][ 64 + hidx];
        float gg = g_sh[r_upd][128 + hidx];
        float go = g_sh[r_upd][192 + hidx];
        float i_ = fast_sigmoid(gi);
        float f_ = fast_sigmoid(gf);
        float g_ = fast_tanh(gg);
        float o_ = fast_sigmoid(go);
        c_state = fmaf(f_, c_state, i_ * g_);
        float h = o_ * fast_tanh(c_state);

        // fused FC accumulation (consume prefetched W_fc row for t)
        p0 = fmaf(h, wf0, p0); p1 = fmaf(h, wf1, p1);
        p2 = fmaf(h, wf2, p2); p3 = fmaf(h, wf3, p3);
        int tn = (t < T_LEN - 1) ? (t + 1) : t;          // prefetch next step
        const float* pfn = W_fc + hidx + tn * H_SZ;
        wf0 = pfn[0]; wf1 = pfn[TH]; wf2 = pfn[2*TH]; wf3 = pfn[3*TH];

        // publish h (guarded by next iteration's first barrier)
        float* hdst = (r_upd < 2) ? (float*)&h01[hidx] : (float*)&h23[hidx];
        hdst[r_upd & 1] = h;
        __syncthreads();
    }

    // --- FC reduction over hidden units + softmax ---
    float* scratch = &g_sh[0][0];   // 1024 floats, reuse
    scratch[(r_upd * 4 + 0) * 64 + hidx] = p0;
    scratch[(r_upd * 4 + 1) * 64 + hidx] = p1;
    scratch[(r_upd * 4 + 2) * 64 + hidx] = p2;
    scratch[(r_upd * 4 + 3) * 64 + hidx] = p3;
    __syncthreads();
    if (j < 16) {
        int nn = j & 3;
        float s = 0.f;
#pragma unroll
        for (int k2 = 0; k2 < 64; k2++) s += scratch[j * 64 + k2];
        logits_sh[j >> 2][nn] = s + b_fc[nn];
    }
    __syncthreads();
    if (j < 4) {
        float l0 = logits_sh[j][0], l1 = logits_sh[j][1];
        float l2 = logits_sh[j][2], l3 = logits_sh[j][3];
        float m  = fmaxf(fmaxf(l0, l1), fmaxf(l2, l3));
        float e0 = __expf(l0 - m), e1 = __expf(l1 - m);
        float e2 = __expf(l2 - m), e3 = __expf(l3 - m);
        float inv = 1.f / (e0 + e1 + e2 + e3);
        float* o = out + (r0 + j) * 4;
        o[0] = e0 * inv; o[1] = e1 * inv; o[2] = e2 * inv; o[3] = e3 * inv;
    }
}

// ---------------------------------------------------------------------------
extern "C" void kernel_launch(void* const* d_in, const int* in_sizes, int n_in,
                              void* d_out, int out_size) {
    const float* x    = (const float*)d_in[0];   // [512, 22, 1000]
    const float* W_ih = (const float*)d_in[1];   // [256, 22]
    const float* W_hh = (const float*)d_in[2];   // [256, 64]
    const float* b_ih = (const float*)d_in[3];   // [256]
    const float* b_hh = (const float*)d_in[4];   // [256]
    const float* W_fc = (const float*)d_in[5];   // [4, 64000]
    const float* b_fc = (const float*)d_in[6];   // [4]
    float* out = (float*)d_out;                  // [512, 4]

    dim3 tgrid((T_LEN + 31) / 32, BC / 32);      // 32 x 352
    dim3 tblk(32, 8);
    transpose_kernel<<<tgrid, tblk>>>(x);

    lstm_fused<<<B_SZ / 4, 256>>>(W_ih, W_hh, b_ih, b_hh, W_fc, b_fc, out);
}

// round 2
// speedup vs baseline: 1.2760x; 1.2760x over previous
#include <cuda_runtime.h>
#include <cstdint>

#define T_LEN 1000
#define B_SZ  512
#define C_IN  22
#define H_SZ  64
#define G4    256
#define BC    (B_SZ * C_IN)   // 11264
#define TH    (T_LEN * H_SZ)  // 64000

typedef unsigned long long ull;

// Scratch: x transposed to [t][b][c] (45 MB static device array)
__device__ float g_xT[T_LEN * BC];

// ---------------------------------------------------------------------------
// Kernel 1: transpose x [B*C, T] -> xT [T, B*C]
// ---------------------------------------------------------------------------
__global__ void transpose_kernel(const float* __restrict__ x) {
    __shared__ float tile[32][33];
    const int tx = threadIdx.x, ty = threadIdx.y;
    const int t0 = blockIdx.x * 32;
    const int r0 = blockIdx.y * 32;
#pragma unroll
    for (int i = 0; i < 32; i += 8) {
        int t = t0 + tx, r = r0 + ty + i;
        if (t < T_LEN) tile[ty + i][tx] = x[r * T_LEN + t];
    }
    __syncthreads();
#pragma unroll
    for (int i = 0; i < 32; i += 8) {
        int t = t0 + ty + i, r = r0 + tx;
        if (t < T_LEN) g_xT[t * BC + r] = tile[tx][ty + i];
    }
}

// ---------------------------------------------------------------------------
// Packed fp32x2 helpers
// ---------------------------------------------------------------------------
__device__ __forceinline__ ull pack2f(float lo, float hi) {
    ull r;
    uint32_t a = __float_as_uint(lo), b = __float_as_uint(hi);
    asm("mov.b64 %0, {%1, %2};" : "=l"(r) : "r"(a), "r"(b));
    return r;
}
__device__ __forceinline__ void ffma2(ull& d, ull a, ull b) {
    asm("fma.rn.f32x2 %0, %1, %2, %3;" : "=l"(d) : "l"(a), "l"(b), "l"(d));
}
__device__ __forceinline__ ull add2(ull a, ull b) {
    ull r;
    asm("add.rn.f32x2 %0, %1, %2;" : "=l"(r) : "l"(a), "l"(b));
    return r;
}
__device__ __forceinline__ void unpack2(ull v, float& lo, float& hi) {
    uint32_t ulo, uhi;
    asm("mov.b64 {%0, %1}, %2;" : "=r"(ulo), "=r"(uhi) : "l"(v));
    lo = __uint_as_float(ulo);
    hi = __uint_as_float(uhi);
}

__device__ __forceinline__ float fast_sigmoid(float v) {
    return __fdividef(1.f, 1.f + __expf(-v));
}
__device__ __forceinline__ float fast_tanh(float v) {
    v = fminf(fmaxf(v, -15.f), 15.f);
    float e = __expf(2.f * v);
    return __fdividef(e - 1.f, e + 1.f);
}

// ---------------------------------------------------------------------------
// Kernel 2: fused LSTM + FC + softmax.
// grid = 256 CTAs (2 batch rows each), 256 threads (one per gate column).
// Hidden-pair f32x2 packing: weights packed ONCE into registers; h/x packed
// in shared. Zero splat movs in the hot loop.
// ---------------------------------------------------------------------------
__global__ void __launch_bounds__(256, 2) lstm_fused(
    const float* __restrict__ W_ih, const float* __restrict__ W_hh,
    const float* __restrict__ b_ih, const float* __restrict__ b_hh,
    const float* __restrict__ W_fc, const float* __restrict__ b_fc,
    float* __restrict__ out)
{
    __shared__ __align__(16) ull hp[2][32];   // h packed by hidden pairs, per row
    __shared__ __align__(16) ull xp[2][12];   // x packed by channel pairs (11 used)
    __shared__ __align__(16) ull g2[G4];      // gates: (row0, row1) per gate col
    __shared__ float red[2 * 4 * 64];         // FC reduction scratch
    __shared__ float logits_sh[2][4];

    const int j  = threadIdx.x;               // gate column 0..255
    const int r0 = blockIdx.x * 2;            // first batch row of this CTA

    // --- pack weights for gate column j into registers (once) ---
    ull whhp[32];
    {
        const float4* wp = reinterpret_cast<const float4*>(W_hh + j * H_SZ);
#pragma unroll
        for (int k = 0; k < 16; k++) {
            float4 v = wp[k];
            whhp[2*k]   = pack2f(v.x, v.y);
            whhp[2*k+1] = pack2f(v.z, v.w);
        }
    }
    ull wihp[11];
    {
        const float2* wp = reinterpret_cast<const float2*>(W_ih + j * C_IN);
#pragma unroll
        for (int c = 0; c < 11; c++) {
            float2 v = wp[c];
            wihp[c] = pack2f(v.x, v.y);
        }
    }
    const float bias = b_ih[j] + b_hh[j];

    // --- init shared h = 0 ---
    if (j < 64) hp[j >> 5][j & 31] = 0ull;

    // --- per-thread recurrent state (threads 0..127): (row r_upd, unit hidx) ---
    const int r_upd = j >> 6;
    const int hidx  = j & 63;
    float c_state = 0.f;
    float p0 = 0.f, p1 = 0.f, p2 = 0.f, p3 = 0.f;

    // W_fc prefetch for t=0
    const float* pf = W_fc + hidx;
    float wf0 = pf[0], wf1 = pf[TH], wf2 = pf[2*TH], wf3 = pf[3*TH];

    // x prefetch for t=0 (threads 0..43: 2 rows x 22 channels, contiguous)
    const float* xrow = g_xT + r0 * C_IN;
    float xreg = 0.f;
    if (j < 44) xreg = xrow[j];

    for (int t = 0; t < T_LEN; t++) {
        // stage x(t) from prefetch register
        if (j < 44) {
            int rr = (j < 22) ? 0 : 1;
            int cc = j - rr * 22;
            ((float*)&xp[rr][cc >> 1])[cc & 1] = xreg;
        }
        __syncthreads();   // BAR1: x(t) + h(t-1) visible

        // prefetch x(t+1) — overlaps the whole gate compute below
        if (j < 44) {
            int tn = (t + 1 < T_LEN) ? t + 1 : t;
            xreg = xrow[tn * BC + j];
        }

        // --- gates for both rows: 4 independent FFMA2 chains, no splats ---
        ull a00 = pack2f(bias, 0.f), a01 = 0ull;   // row 0
        ull a10 = a00,               a11 = 0ull;   // row 1
        const ulonglong2* h0 = reinterpret_cast<const ulonglong2*>(hp[0]);
        const ulonglong2* h1 = reinterpret_cast<const ulonglong2*>(hp[1]);
#pragma unroll
        for (int k = 0; k < 16; k++) {
            ulonglong2 hA = h0[k];
            ulonglong2 hB = h1[k];
            ffma2(a00, whhp[2*k],     hA.x);
            ffma2(a10, whhp[2*k],     hB.x);
            ffma2(a01, whhp[2*k + 1], hA.y);
            ffma2(a11, whhp[2*k + 1], hB.y);
        }
        const ulonglong2* x0 = reinterpret_cast<const ulonglong2*>(xp[0]);
        const ulonglong2* x1 = reinterpret_cast<const ulonglong2*>(xp[1]);
#pragma unroll
        for (int c = 0; c < 5; c++) {
            ulonglong2 xA = x0[c];
            ulonglong2 xB = x1[c];
            ffma2(a00, wihp[2*c],     xA.x);
            ffma2(a10, wihp[2*c],     xB.x);
            ffma2(a01, wihp[2*c + 1], xA.y);
            ffma2(a11, wihp[2*c + 1], xB.y);
        }
        ffma2(a00, wihp[10], xp[0][10]);
        ffma2(a10, wihp[10], xp[1][10]);

        float e0, o0, e1, o1;
        unpack2(add2(a00, a01), e0, o0);
        unpack2(add2(a10, a11), e1, o1);
        g2[j] = pack2f(e0 + o0, e1 + o1);
        __syncthreads();   // BAR2: gates visible

        // --- state update + fused FC (threads 0..127) ---
        if (j < 128) {
            float gi = ((const float*)&g2[        hidx])[r_upd];
            float gf = ((const float*)&g2[ 64 +   hidx])[r_upd];
            float gg = ((const float*)&g2[128 +   hidx])[r_upd];
            float go = ((const float*)&g2[192 +   hidx])[r_upd];
            float i_ = fast_sigmoid(gi);
            float f_ = fast_sigmoid(gf);
            float g_ = fast_tanh(gg);
            float o_ = fast_sigmoid(go);
            c_state = fmaf(f_, c_state, i_ * g_);
            float h = o_ * fast_tanh(c_state);

            p0 = fmaf(h, wf0, p0); p1 = fmaf(h, wf1, p1);
            p2 = fmaf(h, wf2, p2); p3 = fmaf(h, wf3, p3);
            int tn = (t + 1 < T_LEN) ? t + 1 : t;
            const float* pfn = W_fc + hidx + tn * H_SZ;
            wf0 = pfn[0]; wf1 = pfn[TH]; wf2 = pfn[2*TH]; wf3 = pfn[3*TH];

            // publish h(t) (guarded by next iteration's BAR1)
            ((float*)&hp[r_upd][hidx >> 1])[hidx & 1] = h;
        }
        __syncthreads();   // BAR (end of step; pairs with x store at loop top)
    }

    // --- FC reduction + softmax ---
    if (j < 128) {
        red[(r_upd * 4 + 0) * 64 + hidx] = p0;
        red[(r_upd * 4 + 1) * 64 + hidx] = p1;
        red[(r_upd * 4 + 2) * 64 + hidx] = p2;
        red[(r_upd * 4 + 3) * 64 + hidx] = p3;
    }
    __syncthreads();
    if (j < 8) {
        int rr = j >> 2, nn = j & 3;
        float s = 0.f;
#pragma unroll
        for (int k = 0; k < 64; k++) s += red[(rr * 4 + nn) * 64 + k];
        logits_sh[rr][nn] = s + b_fc[nn];
    }
    __syncthreads();
    if (j < 2) {
        float l0 = logits_sh[j][0], l1 = logits_sh[j][1];
        float l2 = logits_sh[j][2], l3 = logits_sh[j][3];
        float m  = fmaxf(fmaxf(l0, l1), fmaxf(l2, l3));
        float q0 = __expf(l0 - m), q1 = __expf(l1 - m);
        float q2 = __expf(l2 - m), q3 = __expf(l3 - m);
        float inv = 1.f / (q0 + q1 + q2 + q3);
        float* o = out + (r0 + j) * 4;
        o[0] = q0 * inv; o[1] = q1 * inv; o[2] = q2 * inv; o[3] = q3 * inv;
    }
}

// ---------------------------------------------------------------------------
extern "C" void kernel_launch(void* const* d_in, const int* in_sizes, int n_in,
                              void* d_out, int out_size) {
    const float* x    = (const float*)d_in[0];
    const float* W_ih = (const float*)d_in[1];
    const float* W_hh = (const float*)d_in[2];
    const float* b_ih = (const float*)d_in[3];
    const float* b_hh = (const float*)d_in[4];
    const float* W_fc = (const float*)d_in[5];
    const float* b_fc = (const float*)d_in[6];
    float* out = (float*)d_out;

    dim3 tgrid((T_LEN + 31) / 32, BC / 32);
    dim3 tblk(32, 8);
    transpose_kernel<<<tgrid, tblk>>>(x);

    lstm_fused<<<B_SZ / 2, 256>>>(W_ih, W_hh, b_ih, b_hh, W_fc, b_fc, out);
}

// round 3
// speedup vs baseline: 1.4866x; 1.1651x over previous
#include <cuda_runtime.h>
#include <cstdint>

#define T_LEN 1000
#define B_SZ  512
#define C_IN  22
#define H_SZ  64
#define G4    256
#define BC    (B_SZ * C_IN)   // 11264
#define TH    (T_LEN * H_SZ)  // 64000

typedef unsigned long long ull;

// Scratch: x transposed to [t][b][c] (45 MB static device array)
__device__ float g_xT[T_LEN * BC];

// ---------------------------------------------------------------------------
// Kernel 1: transpose x [B*C, T] -> xT [T, B*C]
// ---------------------------------------------------------------------------
__global__ void transpose_kernel(const float* __restrict__ x) {
    __shared__ float tile[32][33];
    const int tx = threadIdx.x, ty = threadIdx.y;
    const int t0 = blockIdx.x * 32;
    const int r0 = blockIdx.y * 32;
#pragma unroll
    for (int i = 0; i < 32; i += 8) {
        int t = t0 + tx, r = r0 + ty + i;
        if (t < T_LEN) tile[ty + i][tx] = x[r * T_LEN + t];
    }
    __syncthreads();
#pragma unroll
    for (int i = 0; i < 32; i += 8) {
        int t = t0 + ty + i, r = r0 + tx;
        if (t < T_LEN) g_xT[t * BC + r] = tile[tx][ty + i];
    }
}

// ---------------------------------------------------------------------------
// helpers
// ---------------------------------------------------------------------------
__device__ __forceinline__ ull pack2f(float lo, float hi) {
    ull r;
    uint32_t a = __float_as_uint(lo), b = __float_as_uint(hi);
    asm("mov.b64 %0, {%1, %2};" : "=l"(r) : "r"(a), "r"(b));
    return r;
}
__device__ __forceinline__ void ffma2(ull& d, ull a, ull b) {
    asm("fma.rn.f32x2 %0, %1, %2, %3;" : "=l"(d) : "l"(a), "l"(b), "l"(d));
}
__device__ __forceinline__ ull add2(ull a, ull b) {
    ull r;
    asm("add.rn.f32x2 %0, %1, %2;" : "=l"(r) : "l"(a), "l"(b));
    return r;
}
__device__ __forceinline__ void unpack2(ull v, float& lo, float& hi) {
    uint32_t ulo, uhi;
    asm("mov.b64 {%0, %1}, %2;" : "=r"(ulo), "=r"(uhi) : "l"(v));
    lo = __uint_as_float(ulo);
    hi = __uint_as_float(uhi);
}
__device__ __forceinline__ float tanh_fast(float x) {
    float y;
    asm("tanh.approx.f32 %0, %1;" : "=f"(y) : "f"(x));
    return y;
}

// ---------------------------------------------------------------------------
// Kernel 2: fused LSTM + FC + softmax
// grid = 256 CTAs (2 batch rows each), 256 threads (one gate column each).
// Per step: phase A (all threads) gate GEMV + nonlinearity + x(t+1) staging;
// BAR; phase B (128 threads) state update + FC accum + h publish; BAR.
// ---------------------------------------------------------------------------
__global__ void __launch_bounds__(256, 2) lstm_fused(
    const float* __restrict__ W_ih, const float* __restrict__ W_hh,
    const float* __restrict__ b_ih, const float* __restrict__ b_hh,
    const float* __restrict__ W_fc, const float* __restrict__ b_fc,
    float* __restrict__ out)
{
    __shared__ __align__(16) ull hp[2][32];      // h packed by hidden pairs, per row
    __shared__ __align__(16) ull xp[2][2][12];   // [buf][row][channel pair]
    __shared__ __align__(16) ull g2[G4];         // nonlinearized gates (row0,row1)
    __shared__ float red[2 * 4 * 64];
    __shared__ float logits_sh[2][4];

    const int j  = threadIdx.x;                  // gate column 0..255
    const int r0 = blockIdx.x * 2;

    // --- pack weights for gate column j (once) ---
    ull whhp[32];
    {
        const float4* wp = reinterpret_cast<const float4*>(W_hh + j * H_SZ);
#pragma unroll
        for (int k = 0; k < 16; k++) {
            float4 v = wp[k];
            whhp[2*k]   = pack2f(v.x, v.y);
            whhp[2*k+1] = pack2f(v.z, v.w);
        }
    }
    ull wihp[11];
    {
        const float2* wp = reinterpret_cast<const float2*>(W_ih + j * C_IN);
#pragma unroll
        for (int c = 0; c < 11; c++) {
            float2 v = wp[c];
            wihp[c] = pack2f(v.x, v.y);
        }
    }
    const float bias = b_ih[j] + b_hh[j];

    // nonlinearity params for this gate column: g-gate (cols 128..191) = tanh,
    // others = sigmoid via 0.5 + 0.5*tanh(x/2)
    const bool is_g  = ((j >> 6) == 2);
    const float nl_pre = is_g ? 1.f : 0.5f;
    const float nl_sc  = is_g ? 1.f : 0.5f;
    const float nl_off = is_g ? 0.f : 0.5f;

    // --- init shared state ---
    if (j < 64) hp[j >> 5][j & 31] = 0ull;

    // per-thread recurrent state (threads 0..127): (row r_upd, unit hidx)
    const int r_upd = j >> 6;
    const int hidx  = j & 63;
    float c_state = 0.f;
    float p0 = 0.f, p1 = 0.f, p2 = 0.f, p3 = 0.f;

    // W_fc prefetch for t=0
    const float* pf = W_fc + hidx;
    float wf0 = pf[0], wf1 = pf[TH], wf2 = pf[2*TH], wf3 = pf[3*TH];

    // stage x(0) directly; prefetch x(1) into register
    const float* xrow = g_xT + r0 * C_IN;
    int x_rr = 0, x_cc = 0;
    float xreg = 0.f;
    if (j < 44) {
        x_rr = (j < 22) ? 0 : 1;
        x_cc = j - x_rr * 22;
        ((float*)&xp[0][x_rr][x_cc >> 1])[x_cc & 1] = xrow[j];
        xreg = xrow[BC + j];   // x(1)
    }
    __syncthreads();

    for (int t = 0; t < T_LEN; t++) {
        const int buf = t & 1;

        // ---- phase A: gates (all 256 threads) ----
        ull a00 = pack2f(bias, 0.f), a01 = 0ull;
        ull a10 = a00,               a11 = 0ull;
        const ulonglong2* h0 = reinterpret_cast<const ulonglong2*>(hp[0]);
        const ulonglong2* h1 = reinterpret_cast<const ulonglong2*>(hp[1]);
#pragma unroll
        for (int k = 0; k < 16; k++) {
            ulonglong2 hA = h0[k];
            ulonglong2 hB = h1[k];
            ffma2(a00, whhp[2*k],     hA.x);
            ffma2(a10, whhp[2*k],     hB.x);
            ffma2(a01, whhp[2*k + 1], hA.y);
            ffma2(a11, whhp[2*k + 1], hB.y);
        }
        const ulonglong2* x0 = reinterpret_cast<const ulonglong2*>(xp[buf][0]);
        const ulonglong2* x1 = reinterpret_cast<const ulonglong2*>(xp[buf][1]);
#pragma unroll
        for (int c = 0; c < 5; c++) {
            ulonglong2 xA = x0[c];
            ulonglong2 xB = x1[c];
            ffma2(a00, wihp[2*c],     xA.x);
            ffma2(a10, wihp[2*c],     xB.x);
            ffma2(a01, wihp[2*c + 1], xA.y);
            ffma2(a11, wihp[2*c + 1], xB.y);
        }
        ffma2(a00, wihp[10], xp[buf][0][10]);
        ffma2(a10, wihp[10], xp[buf][1][10]);

        // stage x(t+1) into alternate buffer; prefetch x(t+2)
        if (j < 44) {
            ((float*)&xp[buf ^ 1][x_rr][x_cc >> 1])[x_cc & 1] = xreg;
            int tn = (t + 2 < T_LEN) ? t + 2 : t;
            xreg = xrow[tn * BC + j];
        }

        float e0, o0, e1, o1;
        unpack2(add2(a00, a01), e0, o0);
        unpack2(add2(a10, a11), e1, o1);
        float v0 = e0 + o0, v1 = e1 + o1;
        // nonlinearity here, in parallel across all 256 threads
        float n0 = fmaf(nl_sc, tanh_fast(nl_pre * v0), nl_off);
        float n1 = fmaf(nl_sc, tanh_fast(nl_pre * v1), nl_off);
        g2[j] = pack2f(n0, n1);
        __syncthreads();   // BAR A->B

        // ---- phase B: state update + FC (threads 0..127) ----
        if (j < 128) {
            float i_ = ((const float*)&g2[        hidx])[r_upd];
            float f_ = ((const float*)&g2[ 64 +   hidx])[r_upd];
            float g_ = ((const float*)&g2[128 +   hidx])[r_upd];
            float o_ = ((const float*)&g2[192 +   hidx])[r_upd];
            c_state = fmaf(f_, c_state, i_ * g_);
            float h = o_ * tanh_fast(c_state);

            p0 = fmaf(h, wf0, p0); p1 = fmaf(h, wf1, p1);
            p2 = fmaf(h, wf2, p2); p3 = fmaf(h, wf3, p3);
            int tn = (t + 1 < T_LEN) ? t + 1 : t;
            const float* pfn = W_fc + hidx + tn * H_SZ;
            wf0 = pfn[0]; wf1 = pfn[TH]; wf2 = pfn[2*TH]; wf3 = pfn[3*TH];

            ((float*)&hp[r_upd][hidx >> 1])[hidx & 1] = h;
        }
        __syncthreads();   // BAR B->A (h + staged x visible)
    }

    // ---- FC reduction + softmax ----
    if (j < 128) {
        red[(r_upd * 4 + 0) * 64 + hidx] = p0;
        red[(r_upd * 4 + 1) * 64 + hidx] = p1;
        red[(r_upd * 4 + 2) * 64 + hidx] = p2;
        red[(r_upd * 4 + 3) * 64 + hidx] = p3;
    }
    __syncthreads();
    if (j < 8) {
        int rr = j >> 2, nn = j & 3;
        float s = 0.f;
#pragma unroll
        for (int k = 0; k < 64; k++) s += red[(rr * 4 + nn) * 64 + k];
        logits_sh[rr][nn] = s + b_fc[nn];
    }
    __syncthreads();
    if (j < 2) {
        float l0 = logits_sh[j][0], l1 = logits_sh[j][1];
        float l2 = logits_sh[j][2], l3 = logits_sh[j][3];
        float m  = fmaxf(fmaxf(l0, l1), fmaxf(l2, l3));
        float q0 = __expf(l0 - m), q1 = __expf(l1 - m);
        float q2 = __expf(l2 - m), q3 = __expf(l3 - m);
        float inv = 1.f / (q0 + q1 + q2 + q3);
        float* o = out + (r0 + j) * 4;
        o[0] = q0 * inv; o[1] = q1 * inv; o[2] = q2 * inv; o[3] = q3 * inv;
    }
}

// ---------------------------------------------------------------------------
extern "C" void kernel_launch(void* const* d_in, const int* in_sizes, int n_in,
                              void* d_out, int out_size) {
    const float* x    = (const float*)d_in[0];
    const float* W_ih = (const float*)d_in[1];
    const float* W_hh = (const float*)d_in[2];
    const float* b_ih = (const float*)d_in[3];
    const float* b_hh = (const float*)d_in[4];
    const float* W_fc = (const float*)d_in[5];
    const float* b_fc = (const float*)d_in[6];
    float* out = (float*)d_out;

    dim3 tgrid((T_LEN + 31) / 32, BC / 32);
    dim3 tblk(32, 8);
    transpose_kernel<<<tgrid, tblk>>>(x);

    lstm_fused<<<B_SZ / 2, 256>>>(W_ih, W_hh, b_ih, b_hh, W_fc, b_fc, out);
}